// round 3
// baseline (speedup 1.0000x reference)
#include <cuda_runtime.h>
#include <cuda_bf16.h>
#include <cstdint>

#define T_DIM 32
#define WAY 64
#define SHOT 8
#define QUERY 16
#define C_DIM 1024
#define WQ (WAY * QUERY)   // 1024

#define BM 128
#define BK 64
#define LDS_Q 72   // padded stride (bf16 elems): 144B = 36 banks -> conflict-free frags
#define LDS_P 72

// Scratch (no allocations allowed): proto in bf16 (4 MB) + ||p||^2 in fp32.
__device__ __nv_bfloat16 g_proto[T_DIM * WAY * C_DIM];
__device__ float g_psq[T_DIM * WAY];

// ---------------------------------------------------------------------------
// Kernel 1: prototypes (mean over shots) -> bf16, and p_sq (fp32, from fp32 mean)
// grid (WAY, T), 256 threads; each thread owns 4 contiguous columns.
// ---------------------------------------------------------------------------
__global__ __launch_bounds__(256) void proto_kernel(const float* __restrict__ support) {
    const int way = blockIdx.x;
    const int t   = blockIdx.y;
    const int tid = threadIdx.x;

    const float* base = support + ((size_t)t * WAY * SHOT + (size_t)way * SHOT) * C_DIM + tid * 4;

    float4 s = make_float4(0.f, 0.f, 0.f, 0.f);
#pragma unroll
    for (int sh = 0; sh < SHOT; sh++) {
        float4 v = *(const float4*)(base + (size_t)sh * C_DIM);
        s.x += v.x; s.y += v.y; s.z += v.z; s.w += v.w;
    }
    s.x *= 0.125f; s.y *= 0.125f; s.z *= 0.125f; s.w *= 0.125f;

    // store bf16 proto
    __nv_bfloat162 lo = __floats2bfloat162_rn(s.x, s.y);
    __nv_bfloat162 hi = __floats2bfloat162_rn(s.z, s.w);
    uint2 packed;
    packed.x = *(const uint32_t*)&lo;
    packed.y = *(const uint32_t*)&hi;
    *(uint2*)&g_proto[((size_t)(t * WAY + way)) * C_DIM + tid * 4] = packed;

    // block-reduce sum of squares (fp32 means)
    float ss = s.x * s.x + s.y * s.y + s.z * s.z + s.w * s.w;
#pragma unroll
    for (int off = 16; off > 0; off >>= 1)
        ss += __shfl_xor_sync(0xffffffffu, ss, off);

    __shared__ float red[8];
    if ((tid & 31) == 0) red[tid >> 5] = ss;
    __syncthreads();
    if (tid == 0) {
        float tot = 0.f;
#pragma unroll
        for (int w = 0; w < 8; w++) tot += red[w];
        g_psq[t * WAY + way] = tot;
    }
}

// ---------------------------------------------------------------------------
// mma.sync m16n8k16 bf16 -> f32
// ---------------------------------------------------------------------------
__device__ __forceinline__ void mma16816(float* d, const uint32_t* a, const uint32_t* b) {
    asm volatile(
        "mma.sync.aligned.m16n8k16.row.col.f32.bf16.bf16.f32 "
        "{%0,%1,%2,%3}, {%4,%5,%6,%7}, {%8,%9}, {%0,%1,%2,%3};\n"
        : "+f"(d[0]), "+f"(d[1]), "+f"(d[2]), "+f"(d[3])
        : "r"(a[0]), "r"(a[1]), "r"(a[2]), "r"(a[3]), "r"(b[0]), "r"(b[1]));
}

// ---------------------------------------------------------------------------
// Kernel 2: fused GEMM + norms + epilogue.
// grid (8, T): blockIdx.x = 128-row block of queries, blockIdx.y = t.
// 256 threads = 8 warps (4 M-strips x 2 N-strips of 32x32 each).
// dist = 2*qp - q_sq - p_sq
// ---------------------------------------------------------------------------
__global__ __launch_bounds__(256, 2) void dist_kernel(const float* __restrict__ query,
                                                      float* __restrict__ out) {
    const int t    = blockIdx.y;
    const int rb   = blockIdx.x;
    const int tid  = threadIdx.x;
    const int lane = tid & 31;
    const int warp = tid >> 5;
    const int warpM = warp & 3;   // 0..3 (32-row strips)
    const int warpN = warp >> 2;  // 0..1 (32-col strips)

    __shared__ __align__(16) __nv_bfloat16 sQ[BM * LDS_Q];
    __shared__ __align__(16) __nv_bfloat16 sP[WAY * LDS_P];
    __shared__ float sQsq[BM];
    __shared__ float sPsq[WAY];

    if (tid < WAY) sPsq[tid] = g_psq[t * WAY + tid];

    const float* qbase = query + ((size_t)t * WQ + (size_t)rb * BM) * C_DIM;
    const __nv_bfloat16* pbase = g_proto + (size_t)t * WAY * C_DIM;

    // Q tile load mapping: 16 threads per row, float4 each; 16 rows/pass, 8 passes
    const int rg = tid >> 4;            // 0..15
    const int cc = (tid & 15) * 4;      // fp32 col within BK
    // P tile load mapping: 4 threads per row, 16 bf16 each
    const int prow = tid >> 2;          // 0..63
    const int pcol = (tid & 3) * 16;    // bf16 col within BK

    float4 qreg[8];
    uint4  preg[2];
    float  qsq[8];
    float  acc[2][4][4];
#pragma unroll
    for (int p = 0; p < 8; p++) qsq[p] = 0.f;
#pragma unroll
    for (int mt = 0; mt < 2; mt++)
#pragma unroll
        for (int nt = 0; nt < 4; nt++)
#pragma unroll
            for (int i = 0; i < 4; i++) acc[mt][nt][i] = 0.f;

    // prefetch k-chunk 0
#pragma unroll
    for (int p = 0; p < 8; p++)
        qreg[p] = *(const float4*)(qbase + (size_t)(p * 16 + rg) * C_DIM + cc);
    preg[0] = *(const uint4*)(pbase + (size_t)prow * C_DIM + pcol);
    preg[1] = *(const uint4*)(pbase + (size_t)prow * C_DIM + pcol + 8);

    for (int kk = 0; kk < C_DIM / BK; kk++) {
        // ---- stage registers -> smem (convert Q to bf16, accumulate q^2) ----
#pragma unroll
        for (int p = 0; p < 8; p++) {
            float4 v = qreg[p];
            qsq[p] += v.x * v.x + v.y * v.y + v.z * v.z + v.w * v.w;
            __nv_bfloat162 lo = __floats2bfloat162_rn(v.x, v.y);
            __nv_bfloat162 hi = __floats2bfloat162_rn(v.z, v.w);
            uint2 st;
            st.x = *(const uint32_t*)&lo;
            st.y = *(const uint32_t*)&hi;
            *(uint2*)&sQ[(p * 16 + rg) * LDS_Q + cc] = st;
        }
        *(uint4*)&sP[prow * LDS_P + pcol] = preg[0];
        *(uint4*)&sP[prow * LDS_P + pcol + 8] = preg[1];
        __syncthreads();

        // ---- prefetch next k-chunk while computing on current smem tile ----
        if (kk < C_DIM / BK - 1) {
            const int k0 = (kk + 1) * BK;
#pragma unroll
            for (int p = 0; p < 8; p++)
                qreg[p] = *(const float4*)(qbase + (size_t)(p * 16 + rg) * C_DIM + k0 + cc);
            preg[0] = *(const uint4*)(pbase + (size_t)prow * C_DIM + k0 + pcol);
            preg[1] = *(const uint4*)(pbase + (size_t)prow * C_DIM + k0 + pcol + 8);
        }

        // ---- compute: 4 k16 steps, 2 m-tiles x 4 n-tiles of m16n8k16 ----
#pragma unroll
        for (int ks = 0; ks < 4; ks++) {
            const int kb  = ks * 16;
            const int col = kb + (lane & 3) * 2;
            uint32_t a[2][4], b[4][2];
#pragma unroll
            for (int mt = 0; mt < 2; mt++) {
                const int rr = warpM * 32 + mt * 16 + (lane >> 2);
                a[mt][0] = *(const uint32_t*)&sQ[rr * LDS_Q + col];
                a[mt][1] = *(const uint32_t*)&sQ[(rr + 8) * LDS_Q + col];
                a[mt][2] = *(const uint32_t*)&sQ[rr * LDS_Q + col + 8];
                a[mt][3] = *(const uint32_t*)&sQ[(rr + 8) * LDS_Q + col + 8];
            }
#pragma unroll
            for (int nt = 0; nt < 4; nt++) {
                const int n = warpN * 32 + nt * 8 + (lane >> 2);
                b[nt][0] = *(const uint32_t*)&sP[n * LDS_P + col];
                b[nt][1] = *(const uint32_t*)&sP[n * LDS_P + col + 8];
            }
#pragma unroll
            for (int mt = 0; mt < 2; mt++)
#pragma unroll
                for (int nt = 0; nt < 4; nt++)
                    mma16816(acc[mt][nt], a[mt], b[nt]);
        }
        __syncthreads();
    }

    // ---- reduce q^2 across the 16 column-chunk threads of each row ----
#pragma unroll
    for (int p = 0; p < 8; p++) {
        float v = qsq[p];
        v += __shfl_xor_sync(0xffffffffu, v, 1);
        v += __shfl_xor_sync(0xffffffffu, v, 2);
        v += __shfl_xor_sync(0xffffffffu, v, 4);
        v += __shfl_xor_sync(0xffffffffu, v, 8);
        if ((tid & 15) == 0) sQsq[p * 16 + rg] = v;
    }
    __syncthreads();

    // ---- epilogue: dist = 2*qp - q_sq - p_sq ----
    float* obase = out + ((size_t)t * WQ + (size_t)rb * BM) * WAY;
#pragma unroll
    for (int mt = 0; mt < 2; mt++) {
        const int r0 = warpM * 32 + mt * 16 + (lane >> 2);
        const float qs0 = sQsq[r0];
        const float qs1 = sQsq[r0 + 8];
#pragma unroll
        for (int nt = 0; nt < 4; nt++) {
            const int c0 = warpN * 32 + nt * 8 + (lane & 3) * 2;
            const float ps0 = sPsq[c0];
            const float ps1 = sPsq[c0 + 1];
            float2 d0, d1;
            d0.x = 2.f * acc[mt][nt][0] - qs0 - ps0;
            d0.y = 2.f * acc[mt][nt][1] - qs0 - ps1;
            d1.x = 2.f * acc[mt][nt][2] - qs1 - ps0;
            d1.y = 2.f * acc[mt][nt][3] - qs1 - ps1;
            *(float2*)(obase + (size_t)r0 * WAY + c0) = d0;
            *(float2*)(obase + (size_t)(r0 + 8) * WAY + c0) = d1;
        }
    }
}

extern "C" void kernel_launch(void* const* d_in, const int* in_sizes, int n_in,
                              void* d_out, int out_size) {
    const float* query   = (const float*)d_in[0];   // [32, 1024, 1024]
    const float* support = (const float*)d_in[1];   // [32, 512, 1024]
    float* out = (float*)d_out;                     // [32, 1024, 64]

    proto_kernel<<<dim3(WAY, T_DIM), 256>>>(support);
    dist_kernel<<<dim3(WQ / BM, T_DIM), 256>>>(query, out);
}